// round 2
// baseline (speedup 1.0000x reference)
#include <cuda_runtime.h>
#include <math.h>

#define BB 128
#define NN 512
#define CC 64
#define KNN 16
#define E_TOT (BB*NN*KNN)      /* 1048576 edge elements */
#define NTILES (E_TOT/64)      /* 16384 */
#define LGRID 2048
#define SGRID 512

// ---------------- scratch (static __device__; no allocation) ----------------
__device__ int   g_idx[E_TOT];                 // knn indices (set semantics; order irrelevant downstream)
__device__ float g_PQS[BB*NN*256];             // [b][n][0:64)=P, [64:128)=Q, [128:256)=sc pre-BN
__device__ float g_Wcat[256*64];
__device__ float g_W1t[64*128];                // [c][r]
__device__ float g_W2t[128*128];               // [c][r]
__device__ float g_y1[134217728];              // [e][128] pre-BN layer1 out
__device__ float g_y2[134217728];              // [e][128] pre-BN layer2 out
__device__ float g_part0[SGRID*128];
__device__ float g_partsc[SGRID*256];
__device__ float g_part1[LGRID*256];
__device__ float g_part2[LGRID*256];
__device__ float g_a0[64],  g_c0[64];
__device__ float g_a1[128], g_c1[128];
__device__ float g_a2[128], g_c2[128];
__device__ float g_asc[128], g_csc[128];

// ---------------- prep: fold w0 into (Wc, Wn), transpose w1/w2 ----------------
__global__ void prep_kernel(const float* __restrict__ w0, const float* __restrict__ w1,
                            const float* __restrict__ w2, const float* __restrict__ scw) {
    int tid = threadIdx.x;
    for (int i = tid; i < 64*64; i += 256) {
        int r = i >> 6, c = i & 63;
        g_Wcat[r*64 + c] = w0[r*128 + c] - w0[r*128 + 64 + c];   // Wc = w0a - w0b
    }
    for (int i = tid; i < 64*64; i += 256) {
        int r = i >> 6, c = i & 63;
        g_Wcat[(64 + r)*64 + c] = w0[r*128 + 64 + c];            // Wn = w0b
    }
    for (int i = tid; i < 128*64; i += 256) {
        int r = i >> 6, c = i & 63;
        g_Wcat[(128 + r)*64 + c] = scw[r*64 + c];                // shortcut weight
    }
    for (int i = tid; i < 128*64; i += 256) {
        int r = i & 127, c = i >> 7;
        g_W1t[c*128 + r] = w1[r*64 + c];
    }
    for (int i = tid; i < 128*128; i += 256) {
        int r = i & 127, c = i >> 7;
        g_W2t[c*128 + r] = w2[r*128 + c];
    }
}

// ---------------- kNN: 2-D points, 16 nearest excluding self ----------------
__global__ void knn_kernel(const float* __restrict__ pts) {
    __shared__ float px[512], py[512];
    int b = blockIdx.x, n = threadIdx.x;
    px[n] = pts[b*1024 + n];
    py[n] = pts[b*1024 + 512 + n];
    __syncthreads();
    float x0 = px[n], y0v = py[n];
    float bd[KNN]; int bi[KNN];
#pragma unroll
    for (int i = 0; i < KNN; i++) { bd[i] = 1e30f; bi[i] = 0; }
    for (int m = 0; m < 512; m++) {
        if (m == n) continue;
        float dx = px[m] - x0, dy = py[m] - y0v;
        float d = fmaf(dx, dx, dy*dy);
        if (d < bd[KNN-1]) {
            int j = KNN - 1;
            while (j > 0 && bd[j-1] > d) { bd[j] = bd[j-1]; bi[j] = bi[j-1]; j--; }
            bd[j] = d; bi[j] = m;
        }
    }
    int base = (b*512 + n)*KNN;
#pragma unroll
    for (int k = 0; k < KNN; k++) g_idx[base + k] = bi[k];
}

// ---------------- gemm_f: PQS[b][n][r] = sum_c Wcat[r][c] * f[b][c][n] ----------------
__global__ void gemm_f_kernel(const float* __restrict__ f) {
    __shared__ float Wst[64*65];   // [c][rl]
    __shared__ float fs[64*65];    // [c][nl]
    int tid = threadIdx.x;
    int rt0 = blockIdx.x*64, n0 = blockIdx.y*64, b = blockIdx.z;
#pragma unroll
    for (int s = 0; s < 16; s++) {
        int idx = tid + 256*s;
        int c = idx & 63, rl = idx >> 6;
        Wst[c*65 + rl] = g_Wcat[(rt0 + rl)*64 + c];
    }
#pragma unroll
    for (int s = 0; s < 16; s++) {
        int idx = tid + 256*s;
        int nl = idx & 63, c = idx >> 6;
        fs[c*65 + nl] = f[b*32768 + c*512 + n0 + nl];
    }
    __syncthreads();
    int tx = tid & 15, ty = tid >> 4;
    float acc[4][4];
#pragma unroll
    for (int i = 0; i < 4; i++)
#pragma unroll
        for (int j = 0; j < 4; j++) acc[i][j] = 0.f;
#pragma unroll 4
    for (int c = 0; c < 64; c++) {
        float fv[4];
#pragma unroll
        for (int j = 0; j < 4; j++) fv[j] = fs[c*65 + ty*4 + j];
#pragma unroll
        for (int i = 0; i < 4; i++) {
            float w = Wst[c*65 + tx + 16*i];
#pragma unroll
            for (int j = 0; j < 4; j++) acc[i][j] = fmaf(w, fv[j], acc[i][j]);
        }
    }
#pragma unroll
    for (int j = 0; j < 4; j++) {
        float* dst = &g_PQS[(size_t)(b*512 + n0 + ty*4 + j)*256 + rt0 + tx];
#pragma unroll
        for (int i = 0; i < 4; i++) dst[16*i] = acc[i][j];
    }
}

// ---------------- stats of y0 = P[n] + Q[idx] (64 ch over B*N*K) ----------------
__global__ void stats0_kernel() {
    __shared__ float red[128];
    int tid = threadIdx.x;
    int c = tid & 63, q = tid >> 6;
    float s = 0.f, s2 = 0.f;
    for (int p = blockIdx.x*4 + q; p < BB*NN; p += SGRID*4) {
        float Pv = g_PQS[(size_t)p*256 + c];
        size_t rowbase = (size_t)(p & ~511)*256;
#pragma unroll
        for (int k = 0; k < KNN; k++) {
            int m = g_idx[p*KNN + k];
            float y = Pv + g_PQS[rowbase + (size_t)m*256 + 64 + c];
            s += y; s2 += y*y;
        }
    }
    if (tid < 128) red[tid] = 0.f;
    __syncthreads();
    atomicAdd(&red[c], s);
    atomicAdd(&red[64 + c], s2);
    __syncthreads();
    if (tid < 128) g_part0[blockIdx.x*128 + tid] = red[tid];
}

// ---------------- stats of shortcut pre-BN (128 ch over B*N) ----------------
__global__ void statssc_kernel() {
    __shared__ float red[256];
    int tid = threadIdx.x;
    int c = tid & 127, q = tid >> 7;
    float s = 0.f, s2 = 0.f;
    for (int p = blockIdx.x*2 + q; p < BB*NN; p += SGRID*2) {
        float v = g_PQS[(size_t)p*256 + 128 + c];
        s += v; s2 += v*v;
    }
    red[tid] = 0.f;
    __syncthreads();
    atomicAdd(&red[c], s);
    atomicAdd(&red[128 + c], s2);
    __syncthreads();
    g_partsc[blockIdx.x*256 + tid] = red[tid];
}

// ---------------- finalize: partials -> (a = g*rsqrt(var+eps), c = b - a*mean) ----------------
__global__ void finalize_kernel(const float* __restrict__ part, int nblocks, int nch,
                                const float* __restrict__ g, const float* __restrict__ bt,
                                float minv, float* a_out, float* c_out) {
    int c = threadIdx.x;
    if (c >= nch) return;
    float s = 0.f, s2 = 0.f;
    for (int i = 0; i < nblocks; i++) {
        s  += part[i*2*nch + c];
        s2 += part[i*2*nch + nch + c];
    }
    float mean = s*minv;
    float var = s2*minv - mean*mean;
    float a = g[c] * rsqrtf(var + 1e-5f);
    a_out[c] = a;
    c_out[c] = bt[c] - a*mean;
}

// ---------------- layer1: x1 = relu(a0*(P+Q)+c0); y1 = W1 x1; stats(y1) ----------------
__global__ void __launch_bounds__(256, 2) layer1_kernel() {
    extern __shared__ float sm[];
    float* Wst = sm;            // 64*128
    float* xs  = sm + 64*128;   // 64*65
    __shared__ float sstat[256];
    int tid = threadIdx.x;
    int tx = tid & 15, ty = tid >> 4;
#pragma unroll
    for (int s = 0; s < 32; s++) { int i = tid + 256*s; Wst[i] = g_W1t[i]; }
    int cxl = tid & 63, eg = tid >> 6;
    float a0v = g_a0[cxl], c0v = g_c0[cxl];
    float rs[8], rq[8];
#pragma unroll
    for (int i = 0; i < 8; i++) { rs[i] = 0.f; rq[i] = 0.f; }

    for (int t = blockIdx.x; t < NTILES; t += LGRID) {
        int e0 = t*64;
        __syncthreads();
#pragma unroll
        for (int s = 0; s < 16; s++) {
            int eloc = eg + 4*s;
            int e = e0 + eloc;
            int p = e >> 4;
            int m = g_idx[e];
            float Pv = g_PQS[(size_t)p*256 + cxl];
            float Qv = g_PQS[(size_t)((p & ~511) + m)*256 + 64 + cxl];
            xs[cxl*65 + eloc] = fmaxf(fmaf(a0v, Pv + Qv, c0v), 0.f);
        }
        __syncthreads();
        float acc[8][4];
#pragma unroll
        for (int i = 0; i < 8; i++)
#pragma unroll
            for (int j = 0; j < 4; j++) acc[i][j] = 0.f;
#pragma unroll 4
        for (int c = 0; c < 64; c++) {
            float xv[4];
#pragma unroll
            for (int j = 0; j < 4; j++) xv[j] = xs[c*65 + ty*4 + j];
#pragma unroll
            for (int i = 0; i < 8; i++) {
                float w = Wst[c*128 + tx + 16*i];
#pragma unroll
                for (int j = 0; j < 4; j++) acc[i][j] = fmaf(w, xv[j], acc[i][j]);
            }
        }
#pragma unroll
        for (int j = 0; j < 4; j++) {
            float* dst = &g_y1[(size_t)(e0 + ty*4 + j)*128 + tx];
#pragma unroll
            for (int i = 0; i < 8; i++) {
                float v = acc[i][j];
                dst[16*i] = v;
                rs[i] += v; rq[i] += v*v;
            }
        }
    }
    sstat[tid] = 0.f;
    __syncthreads();
#pragma unroll
    for (int i = 0; i < 8; i++) {
        atomicAdd(&sstat[tx + 16*i], rs[i]);
        atomicAdd(&sstat[128 + tx + 16*i], rq[i]);
    }
    __syncthreads();
    g_part1[blockIdx.x*256 + tid] = sstat[tid];
}

// ---------------- layer2: x2 = relu(a1*y1+c1); y2 = W2 x2; stats(y2) ----------------
__global__ void __launch_bounds__(256, 2) layer2_kernel() {
    extern __shared__ float sm[];
    float* Wst = sm;             // 128*128
    float* xs  = sm + 128*128;   // 128*65
    __shared__ float sstat[256];
    int tid = threadIdx.x;
    int tx = tid & 15, ty = tid >> 4;
#pragma unroll
    for (int s = 0; s < 64; s++) { int i = tid + 256*s; Wst[i] = g_W2t[i]; }
    int cxl = tid & 127, eg = tid >> 7;
    float a1v = g_a1[cxl], c1v = g_c1[cxl];
    float rs[8], rq[8];
#pragma unroll
    for (int i = 0; i < 8; i++) { rs[i] = 0.f; rq[i] = 0.f; }

    for (int t = blockIdx.x; t < NTILES; t += LGRID) {
        int e0 = t*64;
        __syncthreads();
#pragma unroll
        for (int s = 0; s < 32; s++) {
            int eloc = eg + 2*s;
            float v = g_y1[(size_t)(e0 + eloc)*128 + cxl];
            xs[cxl*65 + eloc] = fmaxf(fmaf(a1v, v, c1v), 0.f);
        }
        __syncthreads();
        float acc[8][4];
#pragma unroll
        for (int i = 0; i < 8; i++)
#pragma unroll
            for (int j = 0; j < 4; j++) acc[i][j] = 0.f;
#pragma unroll 2
        for (int c = 0; c < 128; c++) {
            float xv[4];
#pragma unroll
            for (int j = 0; j < 4; j++) xv[j] = xs[c*65 + ty*4 + j];
#pragma unroll
            for (int i = 0; i < 8; i++) {
                float w = Wst[c*128 + tx + 16*i];
#pragma unroll
                for (int j = 0; j < 4; j++) acc[i][j] = fmaf(w, xv[j], acc[i][j]);
            }
        }
#pragma unroll
        for (int j = 0; j < 4; j++) {
            float* dst = &g_y2[(size_t)(e0 + ty*4 + j)*128 + tx];
#pragma unroll
            for (int i = 0; i < 8; i++) {
                float v = acc[i][j];
                dst[16*i] = v;
                rs[i] += v; rq[i] += v*v;
            }
        }
    }
    sstat[tid] = 0.f;
    __syncthreads();
#pragma unroll
    for (int i = 0; i < 8; i++) {
        atomicAdd(&sstat[tx + 16*i], rs[i]);
        atomicAdd(&sstat[128 + tx + 16*i], rq[i]);
    }
    __syncthreads();
    g_part2[blockIdx.x*256 + tid] = sstat[tid];
}

// ---------------- out: fts = mean_k relu(a2*y2+c2); out = relu(asc*sc+csc + fts) ----------------
__global__ void out_kernel(float* __restrict__ out) {
    __shared__ float res[128*33];
    int tid = threadIdx.x;
    int b = blockIdx.x >> 4;
    int n0 = (blockIdx.x & 15)*32;
    int o = tid & 127, ng = tid >> 7;
    float a2v = g_a2[o], c2v = g_c2[o];
    float ascv = g_asc[o], cscv = g_csc[o];
#pragma unroll
    for (int s = 0; s < 16; s++) {
        int nloc = ng + 2*s;
        int p = b*512 + n0 + nloc;
        size_t base = (size_t)p*KNN*128 + o;
        float fts = 0.f;
#pragma unroll
        for (int k = 0; k < KNN; k++)
            fts += fmaxf(fmaf(a2v, g_y2[base + (size_t)k*128], c2v), 0.f);
        fts *= (1.0f/KNN);
        float sc = fmaf(ascv, g_PQS[(size_t)p*256 + 128 + o], cscv);
        res[o*33 + nloc] = fmaxf(sc + fts, 0.f);
    }
    __syncthreads();
#pragma unroll
    for (int s = 0; s < 16; s++) {
        int idx = tid + 256*s;
        int oo = idx >> 5, nl = idx & 31;
        out[(size_t)(b*128 + oo)*512 + n0 + nl] = res[oo*33 + nl];
    }
}

// ---------------- launch ----------------
extern "C" void kernel_launch(void* const* d_in, const int* in_sizes, int n_in,
                              void* d_out, int out_size) {
    const float* pts  = (const float*)d_in[0];
    const float* feat = (const float*)d_in[1];
    const float* w0   = (const float*)d_in[2];
    const float* g0   = (const float*)d_in[3];
    const float* b0   = (const float*)d_in[4];
    const float* w1   = (const float*)d_in[5];
    const float* g1   = (const float*)d_in[6];
    const float* b1   = (const float*)d_in[7];
    const float* w2   = (const float*)d_in[8];
    const float* g2   = (const float*)d_in[9];
    const float* b2   = (const float*)d_in[10];
    const float* scw  = (const float*)d_in[11];
    const float* scg  = (const float*)d_in[12];
    const float* scb  = (const float*)d_in[13];
    float* out = (float*)d_out;

    static_assert(sizeof(float)*(64*128 + 64*65) == 49408, "smem1");
    cudaFuncSetAttribute(layer1_kernel, cudaFuncAttributeMaxDynamicSharedMemorySize, 49408);
    cudaFuncSetAttribute(layer2_kernel, cudaFuncAttributeMaxDynamicSharedMemorySize, 98816);

    float *pa0, *pc0, *pa1, *pc1, *pa2, *pc2, *pasc, *pcsc;
    float *pp0, *ppsc, *pp1, *pp2;
    cudaGetSymbolAddress((void**)&pa0,  g_a0);
    cudaGetSymbolAddress((void**)&pc0,  g_c0);
    cudaGetSymbolAddress((void**)&pa1,  g_a1);
    cudaGetSymbolAddress((void**)&pc1,  g_c1);
    cudaGetSymbolAddress((void**)&pa2,  g_a2);
    cudaGetSymbolAddress((void**)&pc2,  g_c2);
    cudaGetSymbolAddress((void**)&pasc, g_asc);
    cudaGetSymbolAddress((void**)&pcsc, g_csc);
    cudaGetSymbolAddress((void**)&pp0,  g_part0);
    cudaGetSymbolAddress((void**)&ppsc, g_partsc);
    cudaGetSymbolAddress((void**)&pp1,  g_part1);
    cudaGetSymbolAddress((void**)&pp2,  g_part2);

    prep_kernel<<<1, 256>>>(w0, w1, w2, scw);
    knn_kernel<<<BB, 512>>>(pts);
    gemm_f_kernel<<<dim3(4, 8, BB), 256>>>(feat);
    stats0_kernel<<<SGRID, 256>>>();
    statssc_kernel<<<SGRID, 256>>>();
    finalize_kernel<<<1, 64>>>(pp0, SGRID, 64, g0, b0, 1.0f/(float)E_TOT, pa0, pc0);
    finalize_kernel<<<1, 128>>>(ppsc, SGRID, 128, scg, scb, 1.0f/(float)(BB*NN), pasc, pcsc);
    layer1_kernel<<<LGRID, 256, 49408>>>();
    finalize_kernel<<<1, 128>>>(pp1, LGRID, 128, g1, b1, 1.0f/(float)E_TOT, pa1, pc1);
    layer2_kernel<<<LGRID, 256, 98816>>>();
    finalize_kernel<<<1, 128>>>(pp2, LGRID, 128, g2, b2, 1.0f/(float)E_TOT, pa2, pc2);
    out_kernel<<<BB*16, 256>>>(out);

    (void)in_sizes; (void)n_in; (void)out_size;
}

// round 8
// speedup vs baseline: 1.1480x; 1.1480x over previous
#include <cuda_runtime.h>
#include <math.h>

#define BB 128
#define NN 512
#define CC 64
#define KNN 16
#define E_TOT (BB*NN*KNN)      /* 1048576 edge elements */
#define NTILES (E_TOT/64)      /* 16384 */
#define LGRID 2048
#define SGRID 512

typedef unsigned long long u64;

// ---------------- packed f32x2 helpers (sm_103a FFMA2 path) ----------------
__device__ __forceinline__ u64 pack2(float lo, float hi) {
    u64 r; asm("mov.b64 %0, {%1,%2};" : "=l"(r) : "f"(lo), "f"(hi)); return r;
}
__device__ __forceinline__ float2 unpack2(u64 v) {
    float2 r; asm("mov.b64 {%0,%1}, %2;" : "=f"(r.x), "=f"(r.y) : "l"(v)); return r;
}
__device__ __forceinline__ u64 fma2(u64 a, u64 b, u64 c) {
    u64 d; asm("fma.rn.f32x2 %0, %1, %2, %3;" : "=l"(d) : "l"(a), "l"(b), "l"(c)); return d;
}
__device__ __forceinline__ u64 add2(u64 a, u64 b) {
    u64 d; asm("add.rn.f32x2 %0, %1, %2;" : "=l"(d) : "l"(a), "l"(b)); return d;
}
__device__ __forceinline__ u64 lds_b64(unsigned int saddr) {
    u64 d; asm("ld.shared.b64 %0, [%1];" : "=l"(d) : "r"(saddr)); return d;
}

// ---------------- scratch (static __device__; no allocation) ----------------
__device__ int   g_idx[E_TOT];                 // knn indices (set semantics)
__device__ float g_PQS[BB*NN*256];             // [b][n][0:64)=P, [64:128)=Q, [128:256)=sc pre-BN
__device__ float g_Wcat[256*64];
__device__ float g_W1t[64*128];                // [c][r]
__device__ float g_W2t[128*128];               // [c][r]
__device__ float g_y1[134217728];              // [e][128] pre-BN layer1 out
__device__ float g_y2[134217728];              // [e][128] pre-BN layer2 out
__device__ float g_part0[SGRID*128];
__device__ float g_partsc[SGRID*256];
__device__ float g_part1[LGRID*256];
__device__ float g_part2[LGRID*256];
__device__ float g_a0[64],  g_c0[64];
__device__ float g_a1[128], g_c1[128];
__device__ float g_a2[128], g_c2[128];
__device__ float g_asc[128], g_csc[128];

// ---------------- prep: fold w0 into (Wc, Wn), transpose w1/w2 ----------------
__global__ void prep_kernel(const float* __restrict__ w0, const float* __restrict__ w1,
                            const float* __restrict__ w2, const float* __restrict__ scw) {
    int tid = threadIdx.x;
    for (int i = tid; i < 64*64; i += 256) {
        int r = i >> 6, c = i & 63;
        g_Wcat[r*64 + c] = w0[r*128 + c] - w0[r*128 + 64 + c];
    }
    for (int i = tid; i < 64*64; i += 256) {
        int r = i >> 6, c = i & 63;
        g_Wcat[(64 + r)*64 + c] = w0[r*128 + 64 + c];
    }
    for (int i = tid; i < 128*64; i += 256) {
        int r = i >> 6, c = i & 63;
        g_Wcat[(128 + r)*64 + c] = scw[r*64 + c];
    }
    for (int i = tid; i < 128*64; i += 256) {
        int r = i & 127, c = i >> 7;
        g_W1t[c*128 + r] = w1[r*64 + c];
    }
    for (int i = tid; i < 128*128; i += 256) {
        int r = i & 127, c = i >> 7;
        g_W2t[c*128 + r] = w2[r*128 + c];
    }
}

// ---------------- kNN: 2-D points, 16 nearest excluding self ----------------
__global__ void knn_kernel(const float* __restrict__ pts) {
    __shared__ float px[512], py[512];
    int b = blockIdx.x, n = threadIdx.x;
    px[n] = pts[b*1024 + n];
    py[n] = pts[b*1024 + 512 + n];
    __syncthreads();
    float x0 = px[n], y0v = py[n];
    float bd[KNN]; int bi[KNN];
#pragma unroll
    for (int i = 0; i < KNN; i++) { bd[i] = 1e30f; bi[i] = 0; }
    for (int m = 0; m < 512; m++) {
        if (m == n) continue;
        float dx = px[m] - x0, dy = py[m] - y0v;
        float d = fmaf(dx, dx, dy*dy);
        if (d < bd[KNN-1]) {
            int j = KNN - 1;
            while (j > 0 && bd[j-1] > d) { bd[j] = bd[j-1]; bi[j] = bi[j-1]; j--; }
            bd[j] = d; bi[j] = m;
        }
    }
    int base = (b*512 + n)*KNN;
#pragma unroll
    for (int k = 0; k < KNN; k++) g_idx[base + k] = bi[k];
}

// ---------------- gemm_f: PQS[b][n][r] = sum_c Wcat[r][c] * f[b][c][n] ----------------
__global__ void gemm_f_kernel(const float* __restrict__ f) {
    __shared__ float Wst[64*65];   // [c][rl]
    __shared__ float fs[64*65];    // [c][nl]
    int tid = threadIdx.x;
    int rt0 = blockIdx.x*64, n0 = blockIdx.y*64, b = blockIdx.z;
#pragma unroll
    for (int s = 0; s < 16; s++) {
        int idx = tid + 256*s;
        int c = idx & 63, rl = idx >> 6;
        Wst[c*65 + rl] = g_Wcat[(rt0 + rl)*64 + c];
    }
#pragma unroll
    for (int s = 0; s < 16; s++) {
        int idx = tid + 256*s;
        int nl = idx & 63, c = idx >> 6;
        fs[c*65 + nl] = f[b*32768 + c*512 + n0 + nl];
    }
    __syncthreads();
    int tx = tid & 15, ty = tid >> 4;
    float acc[4][4];
#pragma unroll
    for (int i = 0; i < 4; i++)
#pragma unroll
        for (int j = 0; j < 4; j++) acc[i][j] = 0.f;
#pragma unroll 4
    for (int c = 0; c < 64; c++) {
        float fv[4];
#pragma unroll
        for (int j = 0; j < 4; j++) fv[j] = fs[c*65 + ty*4 + j];
#pragma unroll
        for (int i = 0; i < 4; i++) {
            float w = Wst[c*65 + tx + 16*i];
#pragma unroll
            for (int j = 0; j < 4; j++) acc[i][j] = fmaf(w, fv[j], acc[i][j]);
        }
    }
#pragma unroll
    for (int j = 0; j < 4; j++) {
        float* dst = &g_PQS[(size_t)(b*512 + n0 + ty*4 + j)*256 + rt0 + tx];
#pragma unroll
        for (int i = 0; i < 4; i++) dst[16*i] = acc[i][j];
    }
}

// ---------------- stats of y0 = P[n] + Q[idx] (64 ch over B*N*K) ----------------
__global__ void stats0_kernel() {
    __shared__ float red[128];
    int tid = threadIdx.x;
    int c = tid & 63, q = tid >> 6;
    float s = 0.f, s2 = 0.f;
    for (int p = blockIdx.x*4 + q; p < BB*NN; p += SGRID*4) {
        float Pv = g_PQS[(size_t)p*256 + c];
        size_t rowbase = (size_t)(p & ~511)*256;
#pragma unroll
        for (int k = 0; k < KNN; k++) {
            int m = g_idx[p*KNN + k];
            float y = Pv + g_PQS[rowbase + (size_t)m*256 + 64 + c];
            s += y; s2 += y*y;
        }
    }
    if (tid < 128) red[tid] = 0.f;
    __syncthreads();
    atomicAdd(&red[c], s);
    atomicAdd(&red[64 + c], s2);
    __syncthreads();
    if (tid < 128) g_part0[blockIdx.x*128 + tid] = red[tid];
}

// ---------------- stats of shortcut pre-BN (128 ch over B*N) ----------------
__global__ void statssc_kernel() {
    __shared__ float red[256];
    int tid = threadIdx.x;
    int c = tid & 127, q = tid >> 7;
    float s = 0.f, s2 = 0.f;
    for (int p = blockIdx.x*2 + q; p < BB*NN; p += SGRID*2) {
        float v = g_PQS[(size_t)p*256 + 128 + c];
        s += v; s2 += v*v;
    }
    red[tid] = 0.f;
    __syncthreads();
    atomicAdd(&red[c], s);
    atomicAdd(&red[128 + c], s2);
    __syncthreads();
    g_partsc[blockIdx.x*256 + tid] = red[tid];
}

// ---------------- finalize ----------------
__global__ void finalize_kernel(const float* __restrict__ part, int nblocks, int nch,
                                const float* __restrict__ g, const float* __restrict__ bt,
                                float minv, float* a_out, float* c_out) {
    int c = threadIdx.x;
    if (c >= nch) return;
    float s = 0.f, s2 = 0.f;
    for (int i = 0; i < nblocks; i++) {
        s  += part[i*2*nch + c];
        s2 += part[i*2*nch + nch + c];
    }
    float mean = s*minv;
    float var = s2*minv - mean*mean;
    float a = g[c] * rsqrtf(var + 1e-5f);
    a_out[c] = a;
    c_out[c] = bt[c] - a*mean;
}

// xs stride: 68 floats (16B-aligned quads for LDS.128 reads)
#define XP1 68
#define XP2 68

// ---------------- layer1: x1 = relu(a0*(P+Q)+c0); y1 = W1 x1; stats(y1) ----------------
// Thread (tx,ty): owns r-pairs r=2tx+32i (i=0..3), edges j=ty*4..ty*4+3. FFMA2 core.
__global__ void __launch_bounds__(256, 2) layer1_kernel() {
    extern __shared__ float sm[];
    float* Wst = sm;             // 64*128 : [c][r]
    float* xs  = sm + 64*128;    // 64*XP1 : [c][e]
    __shared__ float sstat[256];
    int tid = threadIdx.x;
    int tx = tid & 15, ty = tid >> 4;
    unsigned int wbase = (unsigned int)__cvta_generic_to_shared(Wst) + (2*tx)*4u;
#pragma unroll
    for (int s = 0; s < 32; s++) { int i = tid + 256*s; Wst[i] = g_W1t[i]; }
    int cxl = tid & 63, eg = tid >> 6;
    float a0v = g_a0[cxl], c0v = g_c0[cxl];
    u64 rs[4], rq[4];
#pragma unroll
    for (int i = 0; i < 4; i++) { rs[i] = 0ull; rq[i] = 0ull; }

    for (int t = blockIdx.x; t < NTILES; t += LGRID) {
        int e0 = t*64;
        __syncthreads();
#pragma unroll
        for (int s = 0; s < 16; s++) {
            int eloc = eg + 4*s;
            int e = e0 + eloc;
            int p = e >> 4;
            int m = g_idx[e];
            float Pv = g_PQS[(size_t)p*256 + cxl];
            float Qv = g_PQS[(size_t)((p & ~511) + m)*256 + 64 + cxl];
            xs[cxl*XP1 + eloc] = fmaxf(fmaf(a0v, Pv + Qv, c0v), 0.f);
        }
        __syncthreads();
        u64 acc[4][4];
#pragma unroll
        for (int i = 0; i < 4; i++)
#pragma unroll
            for (int j = 0; j < 4; j++) acc[i][j] = 0ull;
#pragma unroll 8
        for (int c = 0; c < 64; c++) {
            float4 xq = *(const float4*)(xs + c*XP1 + ty*4);
            u64 xd[4];
            xd[0] = pack2(xq.x, xq.x); xd[1] = pack2(xq.y, xq.y);
            xd[2] = pack2(xq.z, xq.z); xd[3] = pack2(xq.w, xq.w);
            u64 wv[4];
#pragma unroll
            for (int i = 0; i < 4; i++) wv[i] = lds_b64(wbase + (c*128 + 32*i)*4u);
#pragma unroll
            for (int i = 0; i < 4; i++)
#pragma unroll
                for (int j = 0; j < 4; j++) acc[i][j] = fma2(wv[i], xd[j], acc[i][j]);
        }
#pragma unroll
        for (int j = 0; j < 4; j++) {
            float* dst = &g_y1[(size_t)(e0 + ty*4 + j)*128 + 2*tx];
#pragma unroll
            for (int i = 0; i < 4; i++) {
                *(float2*)(dst + 32*i) = unpack2(acc[i][j]);
                rs[i] = add2(rs[i], acc[i][j]);
                rq[i] = fma2(acc[i][j], acc[i][j], rq[i]);
            }
        }
    }
    sstat[tid] = 0.f;
    __syncthreads();
#pragma unroll
    for (int i = 0; i < 4; i++) {
        float2 s2 = unpack2(rs[i]);
        float2 q2 = unpack2(rq[i]);
        int ch = 2*tx + 32*i;
        atomicAdd(&sstat[ch],       s2.x);
        atomicAdd(&sstat[ch + 1],   s2.y);
        atomicAdd(&sstat[128 + ch],     q2.x);
        atomicAdd(&sstat[128 + ch + 1], q2.y);
    }
    __syncthreads();
    g_part1[blockIdx.x*256 + tid] = sstat[tid];
}

// ---------------- layer2: x2 = relu(a1*y1+c1); y2 = W2 x2; stats(y2) ----------------
__global__ void __launch_bounds__(256, 2) layer2_kernel() {
    extern __shared__ float sm[];
    float* Wst = sm;              // 128*128 : [c][r]
    float* xs  = sm + 128*128;    // 128*XP2 : [c][e]
    __shared__ float sstat[256];
    int tid = threadIdx.x;
    int tx = tid & 15, ty = tid >> 4;
    unsigned int wbase = (unsigned int)__cvta_generic_to_shared(Wst) + (2*tx)*4u;
#pragma unroll
    for (int s = 0; s < 64; s++) { int i = tid + 256*s; Wst[i] = g_W2t[i]; }
    int cxl = tid & 127, eg = tid >> 7;
    float a1v = g_a1[cxl], c1v = g_c1[cxl];
    u64 rs[4], rq[4];
#pragma unroll
    for (int i = 0; i < 4; i++) { rs[i] = 0ull; rq[i] = 0ull; }

    for (int t = blockIdx.x; t < NTILES; t += LGRID) {
        int e0 = t*64;
        __syncthreads();
#pragma unroll
        for (int s = 0; s < 32; s++) {
            int eloc = eg + 2*s;
            float v = g_y1[(size_t)(e0 + eloc)*128 + cxl];
            xs[cxl*XP2 + eloc] = fmaxf(fmaf(a1v, v, c1v), 0.f);
        }
        __syncthreads();
        u64 acc[4][4];
#pragma unroll
        for (int i = 0; i < 4; i++)
#pragma unroll
            for (int j = 0; j < 4; j++) acc[i][j] = 0ull;
#pragma unroll 8
        for (int c = 0; c < 128; c++) {
            float4 xq = *(const float4*)(xs + c*XP2 + ty*4);
            u64 xd[4];
            xd[0] = pack2(xq.x, xq.x); xd[1] = pack2(xq.y, xq.y);
            xd[2] = pack2(xq.z, xq.z); xd[3] = pack2(xq.w, xq.w);
            u64 wv[4];
#pragma unroll
            for (int i = 0; i < 4; i++) wv[i] = lds_b64(wbase + (c*128 + 32*i)*4u);
#pragma unroll
            for (int i = 0; i < 4; i++)
#pragma unroll
                for (int j = 0; j < 4; j++) acc[i][j] = fma2(wv[i], xd[j], acc[i][j]);
        }
#pragma unroll
        for (int j = 0; j < 4; j++) {
            float* dst = &g_y2[(size_t)(e0 + ty*4 + j)*128 + 2*tx];
#pragma unroll
            for (int i = 0; i < 4; i++) {
                *(float2*)(dst + 32*i) = unpack2(acc[i][j]);
                rs[i] = add2(rs[i], acc[i][j]);
                rq[i] = fma2(acc[i][j], acc[i][j], rq[i]);
            }
        }
    }
    sstat[tid] = 0.f;
    __syncthreads();
#pragma unroll
    for (int i = 0; i < 4; i++) {
        float2 s2 = unpack2(rs[i]);
        float2 q2 = unpack2(rq[i]);
        int ch = 2*tx + 32*i;
        atomicAdd(&sstat[ch],       s2.x);
        atomicAdd(&sstat[ch + 1],   s2.y);
        atomicAdd(&sstat[128 + ch],     q2.x);
        atomicAdd(&sstat[128 + ch + 1], q2.y);
    }
    __syncthreads();
    g_part2[blockIdx.x*256 + tid] = sstat[tid];
}

// ---------------- out ----------------
__global__ void out_kernel(float* __restrict__ out) {
    __shared__ float res[128*33];
    int tid = threadIdx.x;
    int b = blockIdx.x >> 4;
    int n0 = (blockIdx.x & 15)*32;
    int o = tid & 127, ng = tid >> 7;
    float a2v = g_a2[o], c2v = g_c2[o];
    float ascv = g_asc[o], cscv = g_csc[o];
#pragma unroll
    for (int s = 0; s < 16; s++) {
        int nloc = ng + 2*s;
        int p = b*512 + n0 + nloc;
        size_t base = (size_t)p*KNN*128 + o;
        float fts = 0.f;
#pragma unroll
        for (int k = 0; k < KNN; k++)
            fts += fmaxf(fmaf(a2v, g_y2[base + (size_t)k*128], c2v), 0.f);
        fts *= (1.0f/KNN);
        float sc = fmaf(ascv, g_PQS[(size_t)p*256 + 128 + o], cscv);
        res[o*33 + nloc] = fmaxf(sc + fts, 0.f);
    }
    __syncthreads();
#pragma unroll
    for (int s = 0; s < 16; s++) {
        int idx = tid + 256*s;
        int oo = idx >> 5, nl = idx & 31;
        out[(size_t)(b*128 + oo)*512 + n0 + nl] = res[oo*33 + nl];
    }
}

// ---------------- launch ----------------
extern "C" void kernel_launch(void* const* d_in, const int* in_sizes, int n_in,
                              void* d_out, int out_size) {
    const float* pts  = (const float*)d_in[0];
    const float* feat = (const float*)d_in[1];
    const float* w0   = (const float*)d_in[2];
    const float* g0   = (const float*)d_in[3];
    const float* b0   = (const float*)d_in[4];
    const float* w1   = (const float*)d_in[5];
    const float* g1   = (const float*)d_in[6];
    const float* b1   = (const float*)d_in[7];
    const float* w2   = (const float*)d_in[8];
    const float* g2   = (const float*)d_in[9];
    const float* b2   = (const float*)d_in[10];
    const float* scw  = (const float*)d_in[11];
    const float* scg  = (const float*)d_in[12];
    const float* scb  = (const float*)d_in[13];
    float* out = (float*)d_out;

    const int SMEM1 = (64*128 + 64*XP1) * 4;    // 50176
    const int SMEM2 = (128*128 + 128*XP2) * 4;  // 100352
    cudaFuncSetAttribute(layer1_kernel, cudaFuncAttributeMaxDynamicSharedMemorySize, SMEM1);
    cudaFuncSetAttribute(layer2_kernel, cudaFuncAttributeMaxDynamicSharedMemorySize, SMEM2);

    float *pa0, *pc0, *pa1, *pc1, *pa2, *pc2, *pasc, *pcsc;
    float *pp0, *ppsc, *pp1, *pp2;
    cudaGetSymbolAddress((void**)&pa0,  g_a0);
    cudaGetSymbolAddress((void**)&pc0,  g_c0);
    cudaGetSymbolAddress((void**)&pa1,  g_a1);
    cudaGetSymbolAddress((void**)&pc1,  g_c1);
    cudaGetSymbolAddress((void**)&pa2,  g_a2);
    cudaGetSymbolAddress((void**)&pc2,  g_c2);
    cudaGetSymbolAddress((void**)&pasc, g_asc);
    cudaGetSymbolAddress((void**)&pcsc, g_csc);
    cudaGetSymbolAddress((void**)&pp0,  g_part0);
    cudaGetSymbolAddress((void**)&ppsc, g_partsc);
    cudaGetSymbolAddress((void**)&pp1,  g_part1);
    cudaGetSymbolAddress((void**)&pp2,  g_part2);

    prep_kernel<<<1, 256>>>(w0, w1, w2, scw);
    knn_kernel<<<BB, 512>>>(pts);
    gemm_f_kernel<<<dim3(4, 8, BB), 256>>>(feat);
    stats0_kernel<<<SGRID, 256>>>();
    statssc_kernel<<<SGRID, 256>>>();
    finalize_kernel<<<1, 64>>>(pp0, SGRID, 64, g0, b0, 1.0f/(float)E_TOT, pa0, pc0);
    finalize_kernel<<<1, 128>>>(ppsc, SGRID, 128, scg, scb, 1.0f/(float)(BB*NN), pasc, pcsc);
    layer1_kernel<<<LGRID, 256, SMEM1>>>();
    finalize_kernel<<<1, 128>>>(pp1, LGRID, 128, g1, b1, 1.0f/(float)E_TOT, pa1, pc1);
    layer2_kernel<<<LGRID, 256, SMEM2>>>();
    finalize_kernel<<<1, 128>>>(pp2, LGRID, 128, g2, b2, 1.0f/(float)E_TOT, pa2, pc2);
    out_kernel<<<BB*16, 256>>>(out);

    (void)in_sizes; (void)n_in; (void)out_size;
}

// round 10
// speedup vs baseline: 1.2646x; 1.1016x over previous
#include <cuda_runtime.h>
#include <cuda_bf16.h>
#include <math.h>
#include <stdint.h>

#define BB 128
#define NN 512
#define KNN 16
#define E_TOT (BB*NN*KNN)      /* 1048576 edges */
#define NTILES (E_TOT/64)      /* 16384 tiles of 64 edges */
#define L1GRID 592
#define L2GRID 296
#define SGRID 512

// ---------------- helpers ----------------
__device__ __forceinline__ uint32_t smem_u32(const void* p) {
    uint32_t a;
    asm("{ .reg .u64 t; cvta.to.shared.u64 t, %1; cvt.u32.u64 %0, t; }" : "=r"(a) : "l"(p));
    return a;
}
#define LDSM_X4(r, a) \
    asm volatile("ldmatrix.sync.aligned.m8n8.x4.shared.b16 {%0,%1,%2,%3}, [%4];" \
        : "=r"((r)[0]), "=r"((r)[1]), "=r"((r)[2]), "=r"((r)[3]) : "r"(a))
#define LDSM_X2T(r, a) \
    asm volatile("ldmatrix.sync.aligned.m8n8.x2.trans.shared.b16 {%0,%1}, [%2];" \
        : "=r"((r)[0]), "=r"((r)[1]) : "r"(a))
#define MMA_BF16(c, a, b) \
    asm volatile("mma.sync.aligned.m16n8k16.row.col.f32.bf16.bf16.f32 " \
        "{%0,%1,%2,%3}, {%4,%5,%6,%7}, {%8,%9}, {%0,%1,%2,%3};" \
        : "+f"((c)[0]), "+f"((c)[1]), "+f"((c)[2]), "+f"((c)[3]) \
        : "r"((a)[0]), "r"((a)[1]), "r"((a)[2]), "r"((a)[3]), "r"((b)[0]), "r"((b)[1]))

// ---------------- scratch (static __device__; no allocation) ----------------
__device__ int   g_idx[E_TOT];
__device__ float g_PQS[BB*NN*256];          // [p][0:64)=P, [64:128)=Q, [128:256)=sc pre-BN
__device__ float g_Wcat[256*64];
__device__ __align__(16) unsigned short g_w1h[128*72], g_w1l[128*72];     // W1 bf16 hi/lo, stride 72
__device__ __align__(16) unsigned short g_w2h[128*136], g_w2l[128*136];   // W2 bf16 hi/lo, stride 136
__device__ float g_y1[134217728];           // [t][128ch][64e] pre-BN layer1
__device__ float g_y2[134217728];           // [t][128ch][64e] pre-BN layer2
__device__ float g_part0[SGRID*128];
__device__ float g_partsc[SGRID*256];
__device__ float g_part1[2048*256];
__device__ float g_part2[2048*256];
__device__ float g_a0[64],  g_c0[64];
__device__ float g_a1[128], g_c1[128];
__device__ float g_a2[128], g_c2[128];
__device__ float g_asc[128], g_csc[128];

// ---------------- prep: fold w0, split w1/w2 into bf16 hi/lo padded ----------------
__global__ void prep_kernel(const float* __restrict__ w0, const float* __restrict__ w1,
                            const float* __restrict__ w2, const float* __restrict__ scw) {
    int tid = threadIdx.x;
    for (int i = tid; i < 64*64; i += 256) {
        int r = i >> 6, c = i & 63;
        g_Wcat[r*64 + c] = w0[r*128 + c] - w0[r*128 + 64 + c];
    }
    for (int i = tid; i < 64*64; i += 256) {
        int r = i >> 6, c = i & 63;
        g_Wcat[(64 + r)*64 + c] = w0[r*128 + 64 + c];
    }
    for (int i = tid; i < 128*64; i += 256) {
        int r = i >> 6, c = i & 63;
        g_Wcat[(128 + r)*64 + c] = scw[r*64 + c];
    }
    for (int i = tid; i < 128*64; i += 256) {
        int r = i >> 6, c = i & 63;
        float w = w1[r*64 + c];
        __nv_bfloat16 h = __float2bfloat16(w);
        __nv_bfloat16 l = __float2bfloat16(w - __bfloat162float(h));
        g_w1h[r*72 + c] = *reinterpret_cast<unsigned short*>(&h);
        g_w1l[r*72 + c] = *reinterpret_cast<unsigned short*>(&l);
    }
    for (int i = tid; i < 128*128; i += 256) {
        int r = i >> 7, c = i & 127;
        float w = w2[r*128 + c];
        __nv_bfloat16 h = __float2bfloat16(w);
        __nv_bfloat16 l = __float2bfloat16(w - __bfloat162float(h));
        g_w2h[r*136 + c] = *reinterpret_cast<unsigned short*>(&h);
        g_w2l[r*136 + c] = *reinterpret_cast<unsigned short*>(&l);
    }
}

// ---------------- kNN ----------------
__global__ void knn_kernel(const float* __restrict__ pts) {
    __shared__ float px[512], py[512];
    int b = blockIdx.x, n = threadIdx.x;
    px[n] = pts[b*1024 + n];
    py[n] = pts[b*1024 + 512 + n];
    __syncthreads();
    float x0 = px[n], y0v = py[n];
    float bd[KNN]; int bi[KNN];
#pragma unroll
    for (int i = 0; i < KNN; i++) { bd[i] = 1e30f; bi[i] = 0; }
    for (int m = 0; m < 512; m++) {
        if (m == n) continue;
        float dx = px[m] - x0, dy = py[m] - y0v;
        float d = fmaf(dx, dx, dy*dy);
        if (d < bd[KNN-1]) {
            int j = KNN - 1;
            while (j > 0 && bd[j-1] > d) { bd[j] = bd[j-1]; bi[j] = bi[j-1]; j--; }
            bd[j] = d; bi[j] = m;
        }
    }
    int base = (b*512 + n)*KNN;
#pragma unroll
    for (int k = 0; k < KNN; k++) g_idx[base + k] = bi[k];
}

// ---------------- gemm_f: PQS[p][r] = sum_c Wcat[r][c] * f[b][c][n] ----------------
__global__ void gemm_f_kernel(const float* __restrict__ f) {
    __shared__ float Wst[64*65];
    __shared__ float fs[64*65];
    int tid = threadIdx.x;
    int rt0 = blockIdx.x*64, n0 = blockIdx.y*64, b = blockIdx.z;
#pragma unroll
    for (int s = 0; s < 16; s++) {
        int idx = tid + 256*s;
        int c = idx & 63, rl = idx >> 6;
        Wst[c*65 + rl] = g_Wcat[(rt0 + rl)*64 + c];
    }
#pragma unroll
    for (int s = 0; s < 16; s++) {
        int idx = tid + 256*s;
        int nl = idx & 63, c = idx >> 6;
        fs[c*65 + nl] = f[b*32768 + c*512 + n0 + nl];
    }
    __syncthreads();
    int tx = tid & 15, ty = tid >> 4;
    float acc[4][4];
#pragma unroll
    for (int i = 0; i < 4; i++)
#pragma unroll
        for (int j = 0; j < 4; j++) acc[i][j] = 0.f;
#pragma unroll 4
    for (int c = 0; c < 64; c++) {
        float fv[4];
#pragma unroll
        for (int j = 0; j < 4; j++) fv[j] = fs[c*65 + ty*4 + j];
#pragma unroll
        for (int i = 0; i < 4; i++) {
            float w = Wst[c*65 + tx + 16*i];
#pragma unroll
            for (int j = 0; j < 4; j++) acc[i][j] = fmaf(w, fv[j], acc[i][j]);
        }
    }
#pragma unroll
    for (int j = 0; j < 4; j++) {
        float* dst = &g_PQS[(size_t)(b*512 + n0 + ty*4 + j)*256 + rt0 + tx];
#pragma unroll
        for (int i = 0; i < 4; i++) dst[16*i] = acc[i][j];
    }
}

// ---------------- stats of y0 = P[n] + Q[idx] ----------------
__global__ void stats0_kernel() {
    __shared__ float red[128];
    int tid = threadIdx.x;
    int c = tid & 63, q = tid >> 6;
    float s = 0.f, s2 = 0.f;
    for (int p = blockIdx.x*4 + q; p < BB*NN; p += SGRID*4) {
        float Pv = g_PQS[(size_t)p*256 + c];
        size_t rowbase = (size_t)(p & ~511)*256;
#pragma unroll
        for (int k = 0; k < KNN; k++) {
            int m = g_idx[p*KNN + k];
            float y = Pv + g_PQS[rowbase + (size_t)m*256 + 64 + c];
            s += y; s2 += y*y;
        }
    }
    if (tid < 128) red[tid] = 0.f;
    __syncthreads();
    atomicAdd(&red[c], s);
    atomicAdd(&red[64 + c], s2);
    __syncthreads();
    if (tid < 128) g_part0[blockIdx.x*128 + tid] = red[tid];
}

// ---------------- stats of shortcut pre-BN ----------------
__global__ void statssc_kernel() {
    __shared__ float red[256];
    int tid = threadIdx.x;
    int c = tid & 127, q = tid >> 7;
    float s = 0.f, s2 = 0.f;
    for (int p = blockIdx.x*2 + q; p < BB*NN; p += SGRID*2) {
        float v = g_PQS[(size_t)p*256 + 128 + c];
        s += v; s2 += v*v;
    }
    red[tid] = 0.f;
    __syncthreads();
    atomicAdd(&red[c], s);
    atomicAdd(&red[128 + c], s2);
    __syncthreads();
    g_partsc[blockIdx.x*256 + tid] = red[tid];
}

// ---------------- finalize ----------------
__global__ void finalize_kernel(const float* __restrict__ part, int nblocks, int nch,
                                const float* __restrict__ g, const float* __restrict__ bt,
                                float minv, float* a_out, float* c_out) {
    int c = threadIdx.x;
    if (c >= nch) return;
    float s = 0.f, s2 = 0.f;
    for (int i = 0; i < nblocks; i++) {
        s  += part[i*2*nch + c];
        s2 += part[i*2*nch + nch + c];
    }
    float mean = s*minv;
    float var = s2*minv - mean*mean;
    float a = g[c] * rsqrtf(var + 1e-5f);
    a_out[c] = a;
    c_out[c] = bt[c] - a*mean;
}

// ---------------- layer1: mma.sync bf16 split GEMM, K=64 ----------------
// smem: Whi[128*72] Wlo[128*72] Xhi[64*72] Xlo[64*72] (ushort, 144B rows)
__global__ void __launch_bounds__(256) layer1_kernel() {
    extern __shared__ char smraw[];
    unsigned short* Whi = (unsigned short*)smraw;
    unsigned short* Wlo = Whi + 128*72;
    unsigned short* Xhi = Wlo + 128*72;
    unsigned short* Xlo = Xhi + 64*72;
    int tid = threadIdx.x;
    int w = tid >> 5, t = tid & 31;

    {
        uint32_t* dh = (uint32_t*)Whi; uint32_t* dl = (uint32_t*)Wlo;
        const uint32_t* s1 = (const uint32_t*)g_w1h;
        const uint32_t* s2 = (const uint32_t*)g_w1l;
        for (int i = tid; i < 4608; i += 256) { dh[i] = s1[i]; dl[i] = s2[i]; }
    }
    __syncthreads();

    int M0 = w*16;
    uint32_t aoff = (uint32_t)(((M0 + (t & 15))*72 + ((t >> 4) & 1)*8)*2);
    uint32_t awh = smem_u32(Whi) + aoff;
    uint32_t awl = smem_u32(Wlo) + aoff;
    uint32_t bx  = smem_u32(Xhi) + (uint32_t)((t & 15)*144);
    const uint32_t XLO = 64*72*2;   // 9216

    unsigned ahi[4][4];
#pragma unroll
    for (int k = 0; k < 4; k++) LDSM_X4(ahi[k], awh + k*32);

    int c = tid & 63, eg = tid >> 6;
    float a0v = g_a0[c], c0v = g_c0[c];
    int q = t >> 2;
    float rs0 = 0.f, rq0 = 0.f, rs1 = 0.f, rq1 = 0.f;

    for (int tt = blockIdx.x; tt < NTILES; tt += L1GRID) {
        int e0 = tt*64;
#pragma unroll
        for (int s = 0; s < 16; s++) {
            int eloc = eg*16 + s;
            int e = e0 + eloc;
            int p = e >> 4;
            int m = g_idx[e];
            float Pv = g_PQS[(size_t)p*256 + c];
            float Qv = g_PQS[(size_t)((p & ~511) + m)*256 + 64 + c];
            float v = fmaxf(fmaf(a0v, Pv + Qv, c0v), 0.f);
            __nv_bfloat16 h = __float2bfloat16(v);
            __nv_bfloat16 l = __float2bfloat16(v - __bfloat162float(h));
            Xhi[c*72 + eloc] = *reinterpret_cast<unsigned short*>(&h);
            Xlo[c*72 + eloc] = *reinterpret_cast<unsigned short*>(&l);
        }
        __syncthreads();
        float acc[8][4];
#pragma unroll
        for (int j = 0; j < 8; j++)
#pragma unroll
            for (int i = 0; i < 4; i++) acc[j][i] = 0.f;
#pragma unroll
        for (int k = 0; k < 4; k++) {
            unsigned alo[4];
            LDSM_X4(alo, awl + k*32);
#pragma unroll
            for (int j = 0; j < 8; j++) {
                unsigned bh[2], bl[2];
                uint32_t ba = bx + (uint32_t)(k*2304 + j*16);
                LDSM_X2T(bh, ba);
                LDSM_X2T(bl, ba + XLO);
                MMA_BF16(acc[j], ahi[k], bh);
                MMA_BF16(acc[j], ahi[k], bl);
                MMA_BF16(acc[j], alo,    bh);
            }
        }
        __syncthreads();
        int r0 = M0 + q;
        float* b0p = &g_y1[((size_t)tt*128 + r0)*64];
        float* b1p = b0p + 8*64;
#pragma unroll
        for (int j = 0; j < 8; j++) {
            int n = j*8 + ((t & 3) << 1);
            *(float2*)(b0p + n) = make_float2(acc[j][0], acc[j][1]);
            *(float2*)(b1p + n) = make_float2(acc[j][2], acc[j][3]);
            rs0 += acc[j][0] + acc[j][1];
            rq0 += acc[j][0]*acc[j][0] + acc[j][1]*acc[j][1];
            rs1 += acc[j][2] + acc[j][3];
            rq1 += acc[j][2]*acc[j][2] + acc[j][3]*acc[j][3];
        }
    }
    rs0 += __shfl_xor_sync(0xffffffffu, rs0, 1); rs0 += __shfl_xor_sync(0xffffffffu, rs0, 2);
    rq0 += __shfl_xor_sync(0xffffffffu, rq0, 1); rq0 += __shfl_xor_sync(0xffffffffu, rq0, 2);
    rs1 += __shfl_xor_sync(0xffffffffu, rs1, 1); rs1 += __shfl_xor_sync(0xffffffffu, rs1, 2);
    rq1 += __shfl_xor_sync(0xffffffffu, rq1, 1); rq1 += __shfl_xor_sync(0xffffffffu, rq1, 2);
    if ((t & 3) == 0) {
        int r0 = M0 + q;
        g_part1[blockIdx.x*256 + r0]           = rs0;
        g_part1[blockIdx.x*256 + r0 + 8]       = rs1;
        g_part1[blockIdx.x*256 + 128 + r0]     = rq0;
        g_part1[blockIdx.x*256 + 128 + r0 + 8] = rq1;
    }
}

// ---------------- layer2: mma.sync bf16 split GEMM, K=128 ----------------
// smem: Whi[128*136] Wlo[128*136] Xhi[128*72] Xlo[128*72]
__global__ void __launch_bounds__(256) layer2_kernel() {
    extern __shared__ char smraw[];
    unsigned short* Whi = (unsigned short*)smraw;
    unsigned short* Wlo = Whi + 128*136;
    unsigned short* Xhi = Wlo + 128*136;
    unsigned short* Xlo = Xhi + 128*72;
    int tid = threadIdx.x;
    int w = tid >> 5, t = tid & 31;

    {
        uint32_t* dh = (uint32_t*)Whi; uint32_t* dl = (uint32_t*)Wlo;
        const uint32_t* s1 = (const uint32_t*)g_w2h;
        const uint32_t* s2 = (const uint32_t*)g_w2l;
        for (int i = tid; i < 8704; i += 256) { dh[i] = s1[i]; dl[i] = s2[i]; }
    }
    __syncthreads();

    int M0 = w*16;
    uint32_t aoff = (uint32_t)(((M0 + (t & 15))*136 + ((t >> 4) & 1)*8)*2);
    uint32_t awh = smem_u32(Whi) + aoff;
    uint32_t awl = smem_u32(Wlo) + aoff;
    uint32_t bx  = smem_u32(Xhi) + (uint32_t)((t & 15)*144);
    const uint32_t XLO = 128*72*2;   // 18432

    unsigned ahi[8][4];
#pragma unroll
    for (int k = 0; k < 8; k++) LDSM_X4(ahi[k], awh + k*32);

    int q = t >> 2;
    float rs0 = 0.f, rq0 = 0.f, rs1 = 0.f, rq1 = 0.f;

    for (int tt = blockIdx.x; tt < NTILES; tt += L2GRID) {
#pragma unroll
        for (int s = 0; s < 32; s++) {
            int idx = tid + 256*s;
            int k = idx >> 6, e = idx & 63;
            float v = fmaxf(fmaf(g_a1[k], g_y1[((size_t)tt*128 + k)*64 + e], g_c1[k]), 0.f);
            __nv_bfloat16 h = __float2bfloat16(v);
            __nv_bfloat16 l = __float2bfloat16(v - __bfloat162float(h));
            Xhi[k*72 + e] = *reinterpret_cast<unsigned short*>(&h);
            Xlo[k*72 + e] = *reinterpret_cast<unsigned short*>(&l);
        }
        __syncthreads();
        float acc[8][4];
#pragma unroll
        for (int j = 0; j < 8; j++)
#pragma unroll
            for (int i = 0; i < 4; i++) acc[j][i] = 0.f;
#pragma unroll
        for (int k = 0; k < 8; k++) {
            unsigned alo[4];
            LDSM_X4(alo, awl + k*32);
#pragma unroll
            for (int j = 0; j < 8; j++) {
                unsigned bh[2], bl[2];
                uint32_t ba = bx + (uint32_t)(k*2304 + j*16);
                LDSM_X2T(bh, ba);
                LDSM_X2T(bl, ba + XLO);
                MMA_BF16(acc[j], ahi[k], bh);
                MMA_BF16(acc[j], ahi[k], bl);
                MMA_BF16(acc[j], alo,    bh);
            }
        }
        __syncthreads();
        int r0 = M0 + q;
        float* b0p = &g_y2[((size_t)tt*128 + r0)*64];
        float* b1p = b0p + 8*64;
#pragma unroll
        for (int j = 0; j < 8; j++) {
            int n = j*8 + ((t & 3) << 1);
            *(float2*)(b0p + n) = make_float2(acc[j][0], acc[j][1]);
            *(float2*)(b1p + n) = make_float2(acc[j][2], acc[j][3]);
            rs0 += acc[j][0] + acc[j][1];
            rq0 += acc[j][0]*acc[j][0] + acc[j][1]*acc[j][1];
            rs1 += acc[j][2] + acc[j][3];
            rq1 += acc[j][2]*acc[j][2] + acc[j][3]*acc[j][3];
        }
    }
    rs0 += __shfl_xor_sync(0xffffffffu, rs0, 1); rs0 += __shfl_xor_sync(0xffffffffu, rs0, 2);
    rq0 += __shfl_xor_sync(0xffffffffu, rq0, 1); rq0 += __shfl_xor_sync(0xffffffffu, rq0, 2);
    rs1 += __shfl_xor_sync(0xffffffffu, rs1, 1); rs1 += __shfl_xor_sync(0xffffffffu, rs1, 2);
    rq1 += __shfl_xor_sync(0xffffffffu, rq1, 1); rq1 += __shfl_xor_sync(0xffffffffu, rq1, 2);
    if ((t & 3) == 0) {
        int r0 = M0 + q;
        g_part2[blockIdx.x*256 + r0]           = rs0;
        g_part2[blockIdx.x*256 + r0 + 8]       = rs1;
        g_part2[blockIdx.x*256 + 128 + r0]     = rq0;
        g_part2[blockIdx.x*256 + 128 + r0 + 8] = rq1;
    }
}

// ---------------- out: fts = mean_k relu(a2*y2+c2); out = relu(asc*sc+csc + fts) ----------------
__global__ void out_kernel(float* __restrict__ out) {
    __shared__ float res[128*33];
    int tid = threadIdx.x;
    int b = blockIdx.x >> 4;
    int n0 = (blockIdx.x & 15)*32;
    int o = tid & 127, ng = tid >> 7;
    float a2v = g_a2[o], c2v = g_c2[o];
    float ascv = g_asc[o], cscv = g_csc[o];
#pragma unroll
    for (int s = 0; s < 16; s++) {
        int nloc = ng + 2*s;
        int p = b*512 + n0 + nloc;
        int t = p >> 2, q = p & 3;
        const float* yr = &g_y2[((size_t)t*128 + o)*64 + q*16];
        float fts = 0.f;
#pragma unroll
        for (int k = 0; k < KNN; k++)
            fts += fmaxf(fmaf(a2v, yr[k], c2v), 0.f);
        fts *= (1.0f/KNN);
        float sc = fmaf(ascv, g_PQS[(size_t)p*256 + 128 + o], cscv);
        res[o*33 + nloc] = fmaxf(sc + fts, 0.f);
    }
    __syncthreads();
#pragma unroll
    for (int s = 0; s < 16; s++) {
        int idx = tid + 256*s;
        int oo = idx >> 5, nl = idx & 31;
        out[(size_t)(b*128 + oo)*512 + n0 + nl] = res[oo*33 + nl];
    }
}

// ---------------- launch ----------------
extern "C" void kernel_launch(void* const* d_in, const int* in_sizes, int n_in,
                              void* d_out, int out_size) {
    const float* pts  = (const float*)d_in[0];
    const float* feat = (const float*)d_in[1];
    const float* w0   = (const float*)d_in[2];
    const float* g0   = (const float*)d_in[3];
    const float* b0   = (const float*)d_in[4];
    const float* w1   = (const float*)d_in[5];
    const float* g1   = (const float*)d_in[6];
    const float* b1   = (const float*)d_in[7];
    const float* w2   = (const float*)d_in[8];
    const float* g2   = (const float*)d_in[9];
    const float* b2   = (const float*)d_in[10];
    const float* scw  = (const float*)d_in[11];
    const float* scg  = (const float*)d_in[12];
    const float* scb  = (const float*)d_in[13];
    float* out = (float*)d_out;

    const int SMEM1 = (128*72*2 + 64*72*2)*2;   // 55296
    const int SMEM2 = (128*136*2 + 128*72*2)*2; // 106496
    cudaFuncSetAttribute(layer1_kernel, cudaFuncAttributeMaxDynamicSharedMemorySize, SMEM1);
    cudaFuncSetAttribute(layer2_kernel, cudaFuncAttributeMaxDynamicSharedMemorySize, SMEM2);

    float *pa0, *pc0, *pa1, *pc1, *pa2, *pc2, *pasc, *pcsc;
    float *pp0, *ppsc, *pp1, *pp2;
    cudaGetSymbolAddress((void**)&pa0,  g_a0);
    cudaGetSymbolAddress((void**)&pc0,  g_c0);
    cudaGetSymbolAddress((void**)&pa1,  g_a1);
    cudaGetSymbolAddress((void**)&pc1,  g_c1);
    cudaGetSymbolAddress((void**)&pa2,  g_a2);
    cudaGetSymbolAddress((void**)&pc2,  g_c2);
    cudaGetSymbolAddress((void**)&pasc, g_asc);
    cudaGetSymbolAddress((void**)&pcsc, g_csc);
    cudaGetSymbolAddress((void**)&pp0,  g_part0);
    cudaGetSymbolAddress((void**)&ppsc, g_partsc);
    cudaGetSymbolAddress((void**)&pp1,  g_part1);
    cudaGetSymbolAddress((void**)&pp2,  g_part2);

    prep_kernel<<<1, 256>>>(w0, w1, w2, scw);
    knn_kernel<<<BB, 512>>>(pts);
    gemm_f_kernel<<<dim3(4, 8, BB), 256>>>(feat);
    stats0_kernel<<<SGRID, 256>>>();
    statssc_kernel<<<SGRID, 256>>>();
    finalize_kernel<<<1, 64>>>(pp0, SGRID, 64, g0, b0, 1.0f/(float)E_TOT, pa0, pc0);
    finalize_kernel<<<1, 128>>>(ppsc, SGRID, 128, scg, scb, 1.0f/(float)(BB*NN), pasc, pcsc);
    layer1_kernel<<<L1GRID, 256, SMEM1>>>();
    finalize_kernel<<<1, 128>>>(pp1, L1GRID, 128, g1, b1, 1.0f/(float)E_TOT, pa1, pc1);
    layer2_kernel<<<L2GRID, 256, SMEM2>>>();
    finalize_kernel<<<1, 128>>>(pp2, L2GRID, 128, g2, b2, 1.0f/(float)E_TOT, pa2, pc2);
    out_kernel<<<BB*16, 256>>>(out);

    (void)in_sizes; (void)n_in; (void)out_size;
}